// round 2
// baseline (speedup 1.0000x reference)
#include <cuda_runtime.h>

// Problem constants
#define B_    32
#define FIN   64
#define FOUT  64
#define DD    512
#define KK    64
#define KTOT  (KK * DD)      // 32768 (flattened reduction dim of stage-2 GEMM)
#define MM    (B_ * FOUT)    // 2048  (rows of stage-2 GEMM)
#define SPLIT 8
#define KS    (KTOT / SPLIT) // 4096 per split-K chunk

// Scratch: __device__ globals (no allocation anywhere, per harness rules)
__device__ float g_T[(size_t)MM * KTOT];            // 256 MB: T[(b*64+o)][(k*512+e)]
__device__ float g_part[(size_t)SPLIT * MM * DD];   // 32 MB : split-K partials

// ---------------------------------------------------------------------------
// Stage 1: T[b*64+o][k*512+e] = sum_i coeff[o,i,k] * x[b,i,e]
// grid (4 e-chunks of 128, K=64, B=32), 256 threads
// ---------------------------------------------------------------------------
__global__ void __launch_bounds__(256) stage1_kernel(const float* __restrict__ x,
                                                     const float* __restrict__ coeff) {
    const int e0 = blockIdx.x * 128;
    const int k  = blockIdx.y;
    const int b  = blockIdx.z;

    __shared__ __align__(16) float sC[64][68];   // [i][o], padded (row%4==0 for float4, banks split)
    __shared__ __align__(16) float sX[64][128];  // [i][e]

    const int tid = threadIdx.x;

    // Load coeff[:, :, k] transposed -> sC[i][o]   (strided gather; L2-resident, reused over b,e)
    for (int idx = tid; idx < 64 * 64; idx += 256) {
        int o = idx >> 6, i = idx & 63;
        sC[i][o] = coeff[(o * 64 + i) * 64 + k];
    }
    // Load x[b, :, e0:e0+128] -> sX  (coalesced float4)
    for (int idx = tid; idx < 64 * 32; idx += 256) {
        int i = idx >> 5, eq = (idx & 31) << 2;
        *(float4*)&sX[i][eq] = *(const float4*)&x[(b * 64 + i) * 512 + e0 + eq];
    }
    __syncthreads();

    const int tx = tid & 31;   // e-group: 4 e's
    const int ty = tid >> 5;   // o-group: 8 o's

    float acc[8][4];
#pragma unroll
    for (int o = 0; o < 8; ++o)
#pragma unroll
        for (int e = 0; e < 4; ++e) acc[o][e] = 0.0f;

#pragma unroll 8
    for (int i = 0; i < 64; ++i) {
        float4 xv = *(float4*)&sX[i][tx * 4];
        float c[8];
        *(float4*)&c[0] = *(float4*)&sC[i][ty * 8];
        *(float4*)&c[4] = *(float4*)&sC[i][ty * 8 + 4];
#pragma unroll
        for (int o = 0; o < 8; ++o) {
            acc[o][0] += c[o] * xv.x;
            acc[o][1] += c[o] * xv.y;
            acc[o][2] += c[o] * xv.z;
            acc[o][3] += c[o] * xv.w;
        }
    }

    // Store to T: row = b*64 + o, col = k*512 + e0 + e   (coalesced float4 per o-row)
#pragma unroll
    for (int o = 0; o < 8; ++o) {
        size_t row = (size_t)(b * 64 + ty * 8 + o);
        float* dst = g_T + row * KTOT + (size_t)k * 512 + e0 + tx * 4;
        *(float4*)dst = make_float4(acc[o][0], acc[o][1], acc[o][2], acc[o][3]);
    }
}

// ---------------------------------------------------------------------------
// Stage 2: split-K SGEMM  C_part[s] = T[:, s-chunk] @ Wflat[s-chunk, :]
// A = g_T [2048 x 32768] row-major, B = word_ops viewed [32768 x 512] row-major
// BM=128, BN=128, BK=8, 256 threads, 8x8 micro-tiles, double-buffered smem
// grid (N/128=4, M/128=16, SPLIT=8) = 512 blocks
// ---------------------------------------------------------------------------
__global__ void __launch_bounds__(256) sgemm_splitk_kernel(const float* __restrict__ Bmat) {
    const int n0 = blockIdx.x * 128;
    const int m0 = blockIdx.y * 128;
    const int k0 = blockIdx.z * KS;

    __shared__ __align__(16) float sA[2][8][132];  // [k][m], padded: conflict-free scalar stores
    __shared__ __align__(16) float sB[2][8][128];  // [k][n]

    const int tid  = threadIdx.x;
    const int arow = tid >> 1;              // 0..127
    const int akq  = (tid & 1) << 2;        // 0 or 4
    const int bkr  = tid >> 5;              // 0..7
    const int bnq  = (tid & 31) << 2;       // 0..124

    const float* Ap = g_T + (size_t)(m0 + arow) * KTOT + k0 + akq;
    const float* Bp = Bmat + (size_t)(k0 + bkr) * DD + n0 + bnq;

    const int tx = tid & 15;  // n micro-tile: tx*8
    const int ty = tid >> 4;  // m micro-tile: ty*8

    float acc[8][8];
#pragma unroll
    for (int i = 0; i < 8; ++i)
#pragma unroll
        for (int j = 0; j < 8; ++j) acc[i][j] = 0.0f;

    // Prologue: tile 0
    {
        float4 av = *(const float4*)Ap;
        float4 bv = *(const float4*)Bp;
        sA[0][akq + 0][arow] = av.x;
        sA[0][akq + 1][arow] = av.y;
        sA[0][akq + 2][arow] = av.z;
        sA[0][akq + 3][arow] = av.w;
        *(float4*)&sB[0][bkr][bnq] = bv;
    }
    __syncthreads();

    int buf = 0;
    const int NT = KS / 8;  // 512 k-tiles
    for (int kt = 0; kt < NT; ++kt) {
        float4 av2, bv2;
        const bool has_next = (kt + 1 < NT);
        if (has_next) {
            av2 = *(const float4*)(Ap + (kt + 1) * 8);
            bv2 = *(const float4*)(Bp + (size_t)(kt + 1) * 8 * DD);
        }

#pragma unroll
        for (int kk = 0; kk < 8; ++kk) {
            float a[8], bb[8];
            *(float4*)&a[0]  = *(float4*)&sA[buf][kk][ty * 8];
            *(float4*)&a[4]  = *(float4*)&sA[buf][kk][ty * 8 + 4];
            *(float4*)&bb[0] = *(float4*)&sB[buf][kk][tx * 8];
            *(float4*)&bb[4] = *(float4*)&sB[buf][kk][tx * 8 + 4];
#pragma unroll
            for (int i = 0; i < 8; ++i)
#pragma unroll
                for (int j = 0; j < 8; ++j) acc[i][j] += a[i] * bb[j];
        }

        if (has_next) {
            buf ^= 1;
            sA[buf][akq + 0][arow] = av2.x;
            sA[buf][akq + 1][arow] = av2.y;
            sA[buf][akq + 2][arow] = av2.z;
            sA[buf][akq + 3][arow] = av2.w;
            *(float4*)&sB[buf][bkr][bnq] = bv2;
        }
        __syncthreads();
    }

    float* Cp = g_part + (size_t)blockIdx.z * MM * DD;
#pragma unroll
    for (int i = 0; i < 8; ++i) {
        float* row = Cp + (size_t)(m0 + ty * 8 + i) * DD + n0 + tx * 8;
        *(float4*)row       = make_float4(acc[i][0], acc[i][1], acc[i][2], acc[i][3]);
        *(float4*)(row + 4) = make_float4(acc[i][4], acc[i][5], acc[i][6], acc[i][7]);
    }
}

// ---------------------------------------------------------------------------
// Reduce split-K partials into d_out (deterministic; writes every element)
// ---------------------------------------------------------------------------
__global__ void __launch_bounds__(256) reduce_kernel(float* __restrict__ out) {
    const int idx = blockIdx.x * 256 + threadIdx.x;  // float4 index, total 262144
    const float4* p = (const float4*)g_part;
    float4 s = p[idx];
#pragma unroll
    for (int sp = 1; sp < SPLIT; ++sp) {
        float4 v = p[(size_t)sp * (MM * DD / 4) + idx];
        s.x += v.x; s.y += v.y; s.z += v.z; s.w += v.w;
    }
    ((float4*)out)[idx] = s;
}

extern "C" void kernel_launch(void* const* d_in, const int* in_sizes, int n_in,
                              void* d_out, int out_size) {
    const float* x     = (const float*)d_in[0];  // [32,64,512]
    const float* w     = (const float*)d_in[1];  // [64,512,512]
    const float* coeff = (const float*)d_in[2];  // [64,64,64]
    float* out = (float*)d_out;                  // [32,64,512]

    stage1_kernel<<<dim3(4, KK, B_), 256>>>(x, coeff);
    sgemm_splitk_kernel<<<dim3(DD / 128, MM / 128, SPLIT), 256>>>(w);
    reduce_kernel<<<(MM * DD / 4) / 256, 256>>>(out);
}

// round 4
// speedup vs baseline: 1.6688x; 1.6688x over previous
#include <cuda_runtime.h>
#include <cuda_bf16.h>
#include <cstdint>

// ---------------- problem constants ----------------
#define B_    32
#define DD    512
#define KK    64
#define KTOT  32768            // K*D : flattened reduction dim
#define MM    2048             // B*F_out
#define SPLIT 4
#define KPER  (KTOT / SPLIT)   // 8192
#define BK    64               // k elements per pipeline stage (128 bytes bf16)
#define NCH   (KPER / BK)      // 128
#define BM    128
#define BN    256
#define STAGE_BYTES 98304      // Ahi 16K + Alo 16K + Bhi 32K + Blo 32K
#define GEMM_SMEM   (2 * STAGE_BYTES + 1024)

// ---------------- device scratch (no allocation) ----------------
__device__ __nv_bfloat16 g_Ahi[(size_t)MM * KTOT];        // 128 MB
__device__ __nv_bfloat16 g_Alo[(size_t)MM * KTOT];        // 128 MB
__device__ __nv_bfloat16 g_Bhi[(size_t)DD * KTOT];        // 32 MB  (W^T: [d][k*512+e])
__device__ __nv_bfloat16 g_Blo[(size_t)DD * KTOT];        // 32 MB
__device__ float         g_part[(size_t)SPLIT * MM * DD]; // 16 MB

// ---------------- helpers ----------------
__device__ __forceinline__ uint32_t smem_u32(const void* p) {
    uint32_t a;
    asm("{ .reg .u64 t; cvta.to.shared.u64 t, %1; cvt.u32.u64 %0, t; }" : "=r"(a) : "l"(p));
    return a;
}
__device__ __forceinline__ void cp16(uint32_t dst, const void* src) {
    asm volatile("cp.async.cg.shared.global [%0], [%1], 16;" :: "r"(dst), "l"(src));
}
#define CP_COMMIT() asm volatile("cp.async.commit_group;" ::: "memory")
#define CP_WAIT(n)  asm volatile("cp.async.wait_group %0;" :: "n"(n) : "memory")

__device__ __forceinline__ void ldsm4(uint32_t* r, uint32_t addr) {
    asm volatile("ldmatrix.sync.aligned.m8n8.x4.shared.b16 {%0,%1,%2,%3}, [%4];"
                 : "=r"(r[0]), "=r"(r[1]), "=r"(r[2]), "=r"(r[3]) : "r"(addr));
}
__device__ __forceinline__ void mma_bf16(float* c, const uint32_t* a, const uint32_t* b) {
    asm volatile(
        "mma.sync.aligned.m16n8k16.row.col.f32.bf16.bf16.f32 "
        "{%0,%1,%2,%3},{%4,%5,%6,%7},{%8,%9},{%0,%1,%2,%3};"
        : "+f"(c[0]), "+f"(c[1]), "+f"(c[2]), "+f"(c[3])
        : "r"(a[0]), "r"(a[1]), "r"(a[2]), "r"(a[3]), "r"(b[0]), "r"(b[1]));
}

// ---------------------------------------------------------------------------
// Stage 1: T[b*64+o][k*512+e] = sum_i coeff[o,i,k] * x[b,i,e]  -> bf16 hi/lo
// ---------------------------------------------------------------------------
__global__ void __launch_bounds__(256) stage1_kernel(const float* __restrict__ x,
                                                     const float* __restrict__ coeff) {
    const int e0 = blockIdx.x * 128;
    const int k  = blockIdx.y;
    const int b  = blockIdx.z;

    __shared__ __align__(16) float sC[64][68];
    __shared__ __align__(16) float sX[64][128];

    const int tid = threadIdx.x;
    for (int idx = tid; idx < 64 * 64; idx += 256) {
        int o = idx >> 6, i = idx & 63;
        sC[i][o] = coeff[(o * 64 + i) * 64 + k];
    }
    for (int idx = tid; idx < 64 * 32; idx += 256) {
        int i = idx >> 5, eq = (idx & 31) << 2;
        *(float4*)&sX[i][eq] = *(const float4*)&x[(b * 64 + i) * 512 + e0 + eq];
    }
    __syncthreads();

    const int tx = tid & 31;
    const int ty = tid >> 5;

    float acc[8][4];
#pragma unroll
    for (int o = 0; o < 8; ++o)
#pragma unroll
        for (int e = 0; e < 4; ++e) acc[o][e] = 0.0f;

#pragma unroll 8
    for (int i = 0; i < 64; ++i) {
        float4 xv = *(float4*)&sX[i][tx * 4];
        float c[8];
        *(float4*)&c[0] = *(float4*)&sC[i][ty * 8];
        *(float4*)&c[4] = *(float4*)&sC[i][ty * 8 + 4];
#pragma unroll
        for (int o = 0; o < 8; ++o) {
            acc[o][0] += c[o] * xv.x;
            acc[o][1] += c[o] * xv.y;
            acc[o][2] += c[o] * xv.z;
            acc[o][3] += c[o] * xv.w;
        }
    }

#pragma unroll
    for (int o = 0; o < 8; ++o) {
        size_t idx = (size_t)(b * 64 + ty * 8 + o) * KTOT + (size_t)k * 512 + e0 + tx * 4;
        __nv_bfloat16 h[4], l[4];
#pragma unroll
        for (int e = 0; e < 4; ++e) {
            float v = acc[o][e];
            h[e] = __float2bfloat16(v);
            l[e] = __float2bfloat16(v - __bfloat162float(h[e]));
        }
        *(__nv_bfloat162*)&g_Ahi[idx]     = __nv_bfloat162{h[0], h[1]};
        *(__nv_bfloat162*)&g_Ahi[idx + 2] = __nv_bfloat162{h[2], h[3]};
        *(__nv_bfloat162*)&g_Alo[idx]     = __nv_bfloat162{l[0], l[1]};
        *(__nv_bfloat162*)&g_Alo[idx + 2] = __nv_bfloat162{l[2], l[3]};
    }
}

// ---------------------------------------------------------------------------
// W transpose + bf16 hi/lo split: W[(k,e)][d] f32 -> g_Bhi/lo[d][(k,e)]
// ---------------------------------------------------------------------------
__global__ void __launch_bounds__(256) wsplit_kernel(const float* __restrict__ W) {
    __shared__ float s[32][33];
    const int kb = blockIdx.x;      // k-flat / 32
    const int nb = blockIdx.y;      // d / 32
    const int tx = threadIdx.x & 31, tg = threadIdx.x >> 5;

#pragma unroll
    for (int r = 0; r < 4; ++r) {
        int kr = tg + r * 8;
        s[kr][tx] = W[(size_t)(kb * 32 + kr) * DD + nb * 32 + tx];
    }
    __syncthreads();
#pragma unroll
    for (int r = 0; r < 4; ++r) {
        int nr = tg + r * 8;
        float v = s[tx][nr];
        __nv_bfloat16 h = __float2bfloat16(v);
        __nv_bfloat16 l = __float2bfloat16(v - __bfloat162float(h));
        size_t o = (size_t)(nb * 32 + nr) * KTOT + kb * 32 + tx;
        g_Bhi[o] = h;
        g_Blo[o] = l;
    }
}

// ---------------------------------------------------------------------------
// Stage 2: bf16x3 split-K GEMM via mma.sync (HMMA) + ldmatrix + cp.async
// part[s] += (Ahi+Alo)[m][k] * (Bhi+Blo)[n][k]  (drop lo*lo)
// CTA 128x256, BK=64, 8 warps (warp tile 64x64), 2-stage pipeline, SW128 smem.
// grid (2, 16, SPLIT) = 128 CTAs.
// ---------------------------------------------------------------------------
__global__ void __launch_bounds__(256, 1) gemm_kernel() {
    extern __shared__ char smem[];
    const uint32_t sb = (smem_u32(smem) + 1023) & ~1023u;

    const int tid  = threadIdx.x;
    const int lane = tid & 31;
    const int wid  = tid >> 5;
    const int n0 = blockIdx.x * BN;
    const int m0 = blockIdx.y * BM;
    const size_t k0 = (size_t)blockIdx.z * KPER;
    const int warp_m = (wid >> 2) * 64;
    const int warp_n = (wid & 3) * 64;

    // ---- cp.async assignments (per stage: 24 x 16B per thread) ----
    const int ar  = tid >> 1;          // A row 0..127
    const int ac0 = (tid & 1) * 4;     // A 16B-chunk base (0 or 4)
    const __nv_bfloat16* gAhi = g_Ahi + (size_t)(m0 + ar) * KTOT + k0;
    const __nv_bfloat16* gAlo = g_Alo + (size_t)(m0 + ar) * KTOT + k0;
    const __nv_bfloat16* gBhi = g_Bhi + (size_t)(n0 + tid) * KTOT + k0;
    const __nv_bfloat16* gBlo = g_Blo + (size_t)(n0 + tid) * KTOT + k0;

    uint32_t aswz[4], bswz[8];
#pragma unroll
    for (int j = 0; j < 4; ++j)
        aswz[j] = ar * 128 + (((ac0 + j) * 16) ^ ((ar & 7) * 16));
#pragma unroll
    for (int j = 0; j < 8; ++j)
        bswz[j] = tid * 128 + ((j * 16) ^ ((tid & 7) * 16));

    // ---- ldmatrix lane geometry ----
    const int a_row = (lane & 7) | (((lane >> 3) & 1) << 3);
    const int a_k16b = (lane >> 4) * 16;          // 0 or 16 bytes (k+8 half)
    const int b_nr  = (lane & 7) | (((lane >> 4) & 1) << 3);
    const int b_k16b = ((lane >> 3) & 1) * 16;

    float acc[4][8][4];
#pragma unroll
    for (int mt = 0; mt < 4; ++mt)
#pragma unroll
        for (int nt = 0; nt < 8; ++nt)
#pragma unroll
            for (int j = 0; j < 4; ++j) acc[mt][nt][j] = 0.0f;

    auto load_stage = [&](int c, int s) {
        const uint32_t base = sb + s * STAGE_BYTES;
        const int ke = c * BK;   // element offset
#pragma unroll
        for (int j = 0; j < 4; ++j) {
            cp16(base + aswz[j],         gAhi + ke + (ac0 + j) * 8);
            cp16(base + 16384 + aswz[j], gAlo + ke + (ac0 + j) * 8);
        }
#pragma unroll
        for (int j = 0; j < 8; ++j) {
            cp16(base + 32768 + bswz[j], gBhi + ke + j * 8);
            cp16(base + 65536 + bswz[j], gBlo + ke + j * 8);
        }
        CP_COMMIT();
    };

    load_stage(0, 0);

    for (int c = 0; c < NCH; ++c) {
        const int s = c & 1;
        if (c + 1 < NCH) { load_stage(c + 1, s ^ 1); CP_WAIT(1); }
        else             { CP_WAIT(0); }
        __syncthreads();

        const uint32_t Ah = sb + s * STAGE_BYTES;
        const uint32_t Al = Ah + 16384;
        const uint32_t Bh = Ah + 32768;
        const uint32_t Bl = Ah + 65536;

#pragma unroll
        for (int k16 = 0; k16 < 4; ++k16) {
            uint32_t ahi[4][4], alo[4][4], bb[4][4];
#pragma unroll
            for (int mt = 0; mt < 4; ++mt) {
                int r = warp_m + mt * 16 + a_row;
                uint32_t off = r * 128 + ((k16 * 32 + a_k16b) ^ ((r & 7) * 16));
                ldsm4(ahi[mt], Ah + off);
                ldsm4(alo[mt], Al + off);
            }
#pragma unroll
            for (int p = 0; p < 4; ++p) {
                int n = warp_n + p * 16 + b_nr;
                uint32_t off = n * 128 + ((k16 * 32 + b_k16b) ^ ((n & 7) * 16));
                ldsm4(bb[p], Bh + off);
            }
#pragma unroll
            for (int mt = 0; mt < 4; ++mt)
#pragma unroll
                for (int nt = 0; nt < 8; ++nt) {
                    const uint32_t* bfr = &bb[nt >> 1][(nt & 1) * 2];
                    mma_bf16(acc[mt][nt], ahi[mt], bfr);
                    mma_bf16(acc[mt][nt], alo[mt], bfr);
                }
#pragma unroll
            for (int p = 0; p < 4; ++p) {
                int n = warp_n + p * 16 + b_nr;
                uint32_t off = n * 128 + ((k16 * 32 + b_k16b) ^ ((n & 7) * 16));
                ldsm4(bb[p], Bl + off);
            }
#pragma unroll
            for (int mt = 0; mt < 4; ++mt)
#pragma unroll
                for (int nt = 0; nt < 8; ++nt)
                    mma_bf16(acc[mt][nt], ahi[mt], &bb[nt >> 1][(nt & 1) * 2]);
        }
        __syncthreads();
    }

    // ---- epilogue: write fp32 partials ----
    float* Cp = g_part + (size_t)blockIdx.z * MM * DD;
#pragma unroll
    for (int mt = 0; mt < 4; ++mt)
#pragma unroll
        for (int nt = 0; nt < 8; ++nt) {
            int r    = m0 + warp_m + mt * 16 + (lane >> 2);
            int ccol = n0 + warp_n + nt * 8 + (lane & 3) * 2;
            *(float2*)&Cp[(size_t)r * DD + ccol] =
                make_float2(acc[mt][nt][0], acc[mt][nt][1]);
            *(float2*)&Cp[(size_t)(r + 8) * DD + ccol] =
                make_float2(acc[mt][nt][2], acc[mt][nt][3]);
        }
}

// ---------------------------------------------------------------------------
// Reduce split-K partials
// ---------------------------------------------------------------------------
__global__ void __launch_bounds__(256) reduce_kernel(float* __restrict__ out) {
    const int idx = blockIdx.x * 256 + threadIdx.x;
    const float4* p = (const float4*)g_part;
    float4 s = p[idx];
#pragma unroll
    for (int sp = 1; sp < SPLIT; ++sp) {
        float4 v = p[(size_t)sp * (MM * DD / 4) + idx];
        s.x += v.x; s.y += v.y; s.z += v.z; s.w += v.w;
    }
    ((float4*)out)[idx] = s;
}

extern "C" void kernel_launch(void* const* d_in, const int* in_sizes, int n_in,
                              void* d_out, int out_size) {
    const float* x     = (const float*)d_in[0];  // [32,64,512]
    const float* w     = (const float*)d_in[1];  // [64,512,512]
    const float* coeff = (const float*)d_in[2];  // [64,64,64]
    float* out = (float*)d_out;                  // [32,64,512]

    cudaFuncSetAttribute(gemm_kernel, cudaFuncAttributeMaxDynamicSharedMemorySize, GEMM_SMEM);

    stage1_kernel<<<dim3(4, KK, B_), 256>>>(x, coeff);
    wsplit_kernel<<<dim3(KTOT / 32, DD / 32), 256>>>(w);
    gemm_kernel<<<dim3(DD / BN, MM / BM, SPLIT), 256, GEMM_SMEM>>>();
    reduce_kernel<<<(MM * DD / 4) / 256, 256>>>(out);
}

// round 5
// speedup vs baseline: 2.0293x; 1.2161x over previous
#include <cuda_runtime.h>
#include <cuda_fp16.h>
#include <cstdint>

// ---------------- problem constants ----------------
#define B_    32
#define DD    512
#define KK    64
#define KTOT  32768            // K*D : flattened reduction dim
#define MM    2048             // B*F_out
#define SPLIT 4
#define KPER  (KTOT / SPLIT)   // 8192
#define BK    64               // k elems per pipeline stage (128 B rows)
#define NCH   (KPER / BK)      // 128
#define BM    128
#define BN    256
#define STAGE_BYTES 81920      // A 16K + Bhi 32K + Blo 32K
#define GEMM_SMEM   (2 * STAGE_BYTES + 1024)
#define S1_SMEM     (2 * 64 * 68 * 4 + 64 * 128 * 4)   // sC[2] + sX = 67584

// ---------------- device scratch (no allocation) ----------------
__device__ __half g_A[(size_t)MM * KTOT];          // 128 MB (fp16 T)
__device__ __half g_Bhi[(size_t)DD * KTOT];        // 32 MB  (W^T hi)
__device__ __half g_Blo[(size_t)DD * KTOT];        // 32 MB  (W^T lo)
__device__ float  g_part[(size_t)SPLIT * MM * DD]; // 16 MB

// ---------------- helpers ----------------
__device__ __forceinline__ uint32_t smem_u32(const void* p) {
    uint32_t a;
    asm("{ .reg .u64 t; cvta.to.shared.u64 t, %1; cvt.u32.u64 %0, t; }" : "=r"(a) : "l"(p));
    return a;
}
__device__ __forceinline__ void cp16(uint32_t dst, const void* src) {
    asm volatile("cp.async.cg.shared.global [%0], [%1], 16;" :: "r"(dst), "l"(src));
}
#define CP_COMMIT() asm volatile("cp.async.commit_group;" ::: "memory")
#define CP_WAIT(n)  asm volatile("cp.async.wait_group %0;" :: "n"(n) : "memory")

__device__ __forceinline__ void ldsm4(uint32_t* r, uint32_t addr) {
    asm volatile("ldmatrix.sync.aligned.m8n8.x4.shared.b16 {%0,%1,%2,%3}, [%4];"
                 : "=r"(r[0]), "=r"(r[1]), "=r"(r[2]), "=r"(r[3]) : "r"(addr));
}
__device__ __forceinline__ void mma_f16(float* c, const uint32_t* a, const uint32_t* b) {
    asm volatile(
        "mma.sync.aligned.m16n8k16.row.col.f32.f16.f16.f32 "
        "{%0,%1,%2,%3},{%4,%5,%6,%7},{%8,%9},{%0,%1,%2,%3};"
        : "+f"(c[0]), "+f"(c[1]), "+f"(c[2]), "+f"(c[3])
        : "r"(a[0]), "r"(a[1]), "r"(a[2]), "r"(a[3]), "r"(b[0]), "r"(b[1]));
}

// ---------------------------------------------------------------------------
// Stage 1: T[b*64+o][k*512+e] = sum_i coeff[o,i,k] * x[b,i,e]  -> fp16
// block: (e-block of 128, k-pair, b), 256 threads, micro-tile 8o x 4e x 2k
// ---------------------------------------------------------------------------
__global__ void __launch_bounds__(256) stage1_kernel(const float* __restrict__ x,
                                                     const float* __restrict__ coeff) {
    extern __shared__ float s1[];
    float (*sC)[64][68] = (float (*)[64][68])s1;          // [2][i][o]
    float (*sX)[128]    = (float (*)[128])(s1 + 2 * 64 * 68);  // [i][e]

    const int e0 = blockIdx.x * 128;
    const int kp = blockIdx.y;           // k-pair: k = 2*kp + {0,1}
    const int b  = blockIdx.z;
    const int tid = threadIdx.x;

    // coeff[:, :, 2kp+kk] -> sC[kk][i][o]   (L2-resident strided gather)
    for (int idx = tid; idx < 2 * 64 * 64; idx += 256) {
        int kk = idx >> 12, rem = idx & 4095;
        int o = rem >> 6, i = rem & 63;
        sC[kk][i][o] = coeff[(o * 64 + i) * 64 + kp * 2 + kk];
    }
    // x[b, :, e0:e0+128] -> sX
    for (int idx = tid; idx < 64 * 32; idx += 256) {
        int i = idx >> 5, eq = (idx & 31) << 2;
        *(float4*)&sX[i][eq] = *(const float4*)&x[(b * 64 + i) * 512 + e0 + eq];
    }
    __syncthreads();

    const int tx = tid & 31;   // e-group: 4 e's
    const int ty = tid >> 5;   // o-group: 8 o's

    float acc[2][8][4];
#pragma unroll
    for (int kk = 0; kk < 2; ++kk)
#pragma unroll
        for (int o = 0; o < 8; ++o)
#pragma unroll
            for (int e = 0; e < 4; ++e) acc[kk][o][e] = 0.0f;

#pragma unroll 4
    for (int i = 0; i < 64; ++i) {
        float4 xv = *(float4*)&sX[i][tx * 4];
        float c0[8], c1[8];
        *(float4*)&c0[0] = *(float4*)&sC[0][i][ty * 8];
        *(float4*)&c0[4] = *(float4*)&sC[0][i][ty * 8 + 4];
        *(float4*)&c1[0] = *(float4*)&sC[1][i][ty * 8];
        *(float4*)&c1[4] = *(float4*)&sC[1][i][ty * 8 + 4];
#pragma unroll
        for (int o = 0; o < 8; ++o) {
            acc[0][o][0] += c0[o] * xv.x;  acc[0][o][1] += c0[o] * xv.y;
            acc[0][o][2] += c0[o] * xv.z;  acc[0][o][3] += c0[o] * xv.w;
            acc[1][o][0] += c1[o] * xv.x;  acc[1][o][1] += c1[o] * xv.y;
            acc[1][o][2] += c1[o] * xv.z;  acc[1][o][3] += c1[o] * xv.w;
        }
    }

#pragma unroll
    for (int kk = 0; kk < 2; ++kk)
#pragma unroll
        for (int o = 0; o < 8; ++o) {
            size_t idx = (size_t)(b * 64 + ty * 8 + o) * KTOT +
                         (size_t)(kp * 2 + kk) * 512 + e0 + tx * 4;
            __half2 p0 = __floats2half2_rn(acc[kk][o][0], acc[kk][o][1]);
            __half2 p1 = __floats2half2_rn(acc[kk][o][2], acc[kk][o][3]);
            *(__half2*)&g_A[idx]     = p0;
            *(__half2*)&g_A[idx + 2] = p1;
        }
}

// ---------------------------------------------------------------------------
// W transpose + fp16 hi/lo split: W[(k,e)][d] f32 -> g_Bhi/lo[d][(k,e)]
// ---------------------------------------------------------------------------
__global__ void __launch_bounds__(256) wsplit_kernel(const float* __restrict__ W) {
    __shared__ float s[32][33];
    const int kb = blockIdx.x;      // k-flat / 32
    const int nb = blockIdx.y;      // d / 32
    const int tx = threadIdx.x & 31, tg = threadIdx.x >> 5;

#pragma unroll
    for (int r = 0; r < 4; ++r) {
        int kr = tg + r * 8;
        s[kr][tx] = W[(size_t)(kb * 32 + kr) * DD + nb * 32 + tx];
    }
    __syncthreads();
#pragma unroll
    for (int r = 0; r < 4; ++r) {
        int nr = tg + r * 8;
        float v = s[tx][nr];
        __half h = __float2half_rn(v);
        __half l = __float2half_rn(v - __half2float(h));
        size_t o = (size_t)(nb * 32 + nr) * KTOT + kb * 32 + tx;
        g_Bhi[o] = h;
        g_Blo[o] = l;
    }
}

// ---------------------------------------------------------------------------
// Stage 2: fp16 2-MMA split-K GEMM:  part += A * (Bhi + Blo)
// CTA 128x256, BK=64, 8 warps (64x64 warp tile), 2-stage cp.async, SW128 smem.
// grid (2, 16, SPLIT) = 128 CTAs.
// ---------------------------------------------------------------------------
__global__ void __launch_bounds__(256, 1) gemm_kernel() {
    extern __shared__ char smem[];
    const uint32_t sb = (smem_u32(smem) + 1023) & ~1023u;

    const int tid  = threadIdx.x;
    const int lane = tid & 31;
    const int wid  = tid >> 5;
    const int n0 = blockIdx.x * BN;
    const int m0 = blockIdx.y * BM;
    const size_t k0 = (size_t)blockIdx.z * KPER;
    const int warp_m = (wid >> 2) * 64;
    const int warp_n = (wid & 3) * 64;

    // ---- cp.async assignments ----
    const int ar  = tid >> 1;          // A row 0..127
    const int ac0 = (tid & 1) * 4;     // A 16B-chunk base
    const __half* gA   = g_A   + (size_t)(m0 + ar) * KTOT + k0;
    const __half* gBhi = g_Bhi + (size_t)(n0 + tid) * KTOT + k0;
    const __half* gBlo = g_Blo + (size_t)(n0 + tid) * KTOT + k0;

    uint32_t aswz[4], bswz[8];
#pragma unroll
    for (int j = 0; j < 4; ++j)
        aswz[j] = ar * 128 + (((ac0 + j) * 16) ^ ((ar & 7) * 16));
#pragma unroll
    for (int j = 0; j < 8; ++j)
        bswz[j] = tid * 128 + ((j * 16) ^ ((tid & 7) * 16));

    // ---- ldmatrix lane geometry ----
    const int a_row  = (lane & 7) | (((lane >> 3) & 1) << 3);
    const int a_k16b = (lane >> 4) * 16;
    const int b_nr   = (lane & 7) | (((lane >> 4) & 1) << 3);
    const int b_k16b = ((lane >> 3) & 1) * 16;

    float acc[4][8][4];
#pragma unroll
    for (int mt = 0; mt < 4; ++mt)
#pragma unroll
        for (int nt = 0; nt < 8; ++nt)
#pragma unroll
            for (int j = 0; j < 4; ++j) acc[mt][nt][j] = 0.0f;

    auto load_stage = [&](int c, int s) {
        const uint32_t base = sb + s * STAGE_BYTES;
        const int ke = c * BK;
#pragma unroll
        for (int j = 0; j < 4; ++j)
            cp16(base + aswz[j], gA + ke + (ac0 + j) * 8);
#pragma unroll
        for (int j = 0; j < 8; ++j) {
            cp16(base + 16384 + bswz[j], gBhi + ke + j * 8);
            cp16(base + 49152 + bswz[j], gBlo + ke + j * 8);
        }
        CP_COMMIT();
    };

    load_stage(0, 0);

    for (int c = 0; c < NCH; ++c) {
        const int s = c & 1;
        if (c + 1 < NCH) { load_stage(c + 1, s ^ 1); CP_WAIT(1); }
        else             { CP_WAIT(0); }
        __syncthreads();

        const uint32_t Ab = sb + s * STAGE_BYTES;
        const uint32_t Bh = Ab + 16384;
        const uint32_t Bl = Ab + 49152;

#pragma unroll
        for (int k16 = 0; k16 < 4; ++k16) {
            uint32_t a[4][4], bh[4][4], bl[4][4];
#pragma unroll
            for (int mt = 0; mt < 4; ++mt) {
                int r = warp_m + mt * 16 + a_row;
                uint32_t off = r * 128 + ((k16 * 32 + a_k16b) ^ ((r & 7) * 16));
                ldsm4(a[mt], Ab + off);
            }
#pragma unroll
            for (int p = 0; p < 4; ++p) {
                int n = warp_n + p * 16 + b_nr;
                uint32_t off = n * 128 + ((k16 * 32 + b_k16b) ^ ((n & 7) * 16));
                ldsm4(bh[p], Bh + off);
                ldsm4(bl[p], Bl + off);
            }
#pragma unroll
            for (int mt = 0; mt < 4; ++mt)
#pragma unroll
                for (int nt = 0; nt < 8; ++nt) {
                    mma_f16(acc[mt][nt], a[mt], &bh[nt >> 1][(nt & 1) * 2]);
                    mma_f16(acc[mt][nt], a[mt], &bl[nt >> 1][(nt & 1) * 2]);
                }
        }
        __syncthreads();
    }

    // ---- epilogue: fp32 partials ----
    float* Cp = g_part + (size_t)blockIdx.z * MM * DD;
#pragma unroll
    for (int mt = 0; mt < 4; ++mt)
#pragma unroll
        for (int nt = 0; nt < 8; ++nt) {
            int r    = m0 + warp_m + mt * 16 + (lane >> 2);
            int ccol = n0 + warp_n + nt * 8 + (lane & 3) * 2;
            *(float2*)&Cp[(size_t)r * DD + ccol] =
                make_float2(acc[mt][nt][0], acc[mt][nt][1]);
            *(float2*)&Cp[(size_t)(r + 8) * DD + ccol] =
                make_float2(acc[mt][nt][2], acc[mt][nt][3]);
        }
}

// ---------------------------------------------------------------------------
// Reduce split-K partials
// ---------------------------------------------------------------------------
__global__ void __launch_bounds__(256) reduce_kernel(float* __restrict__ out) {
    const int idx = blockIdx.x * 256 + threadIdx.x;
    const float4* p = (const float4*)g_part;
    float4 s = p[idx];
#pragma unroll
    for (int sp = 1; sp < SPLIT; ++sp) {
        float4 v = p[(size_t)sp * (MM * DD / 4) + idx];
        s.x += v.x; s.y += v.y; s.z += v.z; s.w += v.w;
    }
    ((float4*)out)[idx] = s;
}

extern "C" void kernel_launch(void* const* d_in, const int* in_sizes, int n_in,
                              void* d_out, int out_size) {
    const float* x     = (const float*)d_in[0];  // [32,64,512]
    const float* w     = (const float*)d_in[1];  // [64,512,512]
    const float* coeff = (const float*)d_in[2];  // [64,64,64]
    float* out = (float*)d_out;                  // [32,64,512]

    cudaFuncSetAttribute(gemm_kernel,   cudaFuncAttributeMaxDynamicSharedMemorySize, GEMM_SMEM);
    cudaFuncSetAttribute(stage1_kernel, cudaFuncAttributeMaxDynamicSharedMemorySize, S1_SMEM);

    stage1_kernel<<<dim3(4, KK / 2, B_), 256, S1_SMEM>>>(x, coeff);
    wsplit_kernel<<<dim3(KTOT / 32, DD / 32), 256>>>(w);
    gemm_kernel<<<dim3(DD / BN, MM / BM, SPLIT), 256, GEMM_SMEM>>>();
    reduce_kernel<<<(MM * DD / 4) / 256, 256>>>(out);
}

// round 6
// speedup vs baseline: 4.4262x; 2.1812x over previous
#include <cuda_runtime.h>
#include <cuda_fp16.h>
#include <cstdint>

// ---------------- problem constants ----------------
#define B_    32
#define DD    512
#define KK    64
#define KTOT  32768            // K*D : flattened reduction dim
#define MM    2048             // B*F_out
#define SPLIT 4
#define KPER  (KTOT / SPLIT)   // 8192
#define BK    64               // k elems per pipeline stage (128 B rows)
#define NCH   (KPER / BK)      // 128
#define BM    128
#define BN    256
#define NSTG  3
#define STAGE_BYTES 49152      // A 16K + B 32K
#define GEMM_SMEM   (NSTG * STAGE_BYTES + 1024)
#define S1_SMEM     131072     // sX 64K + sC 64K

// ---------------- device scratch (no allocation) ----------------
__device__ __half g_A[(size_t)MM * KTOT];          // 128 MB (fp16 T)
__device__ __half g_B[(size_t)DD * KTOT];          // 32 MB  (W^T fp16)
__device__ __half g_C[(size_t)KK * 64 * 64];       // 512 KB (coeff [k][o][i] fp16)
__device__ float  g_part[(size_t)SPLIT * MM * DD]; // 16 MB

// ---------------- helpers ----------------
__device__ __forceinline__ uint32_t smem_u32(const void* p) {
    uint32_t a;
    asm("{ .reg .u64 t; cvta.to.shared.u64 t, %1; cvt.u32.u64 %0, t; }" : "=r"(a) : "l"(p));
    return a;
}
__device__ __forceinline__ void cp16(uint32_t dst, const void* src) {
    asm volatile("cp.async.cg.shared.global [%0], [%1], 16;" :: "r"(dst), "l"(src));
}
#define CP_COMMIT() asm volatile("cp.async.commit_group;" ::: "memory")
#define CP_WAIT(n)  asm volatile("cp.async.wait_group %0;" :: "n"(n) : "memory")

__device__ __forceinline__ void ldsm4(uint32_t* r, uint32_t addr) {
    asm volatile("ldmatrix.sync.aligned.m8n8.x4.shared.b16 {%0,%1,%2,%3}, [%4];"
                 : "=r"(r[0]), "=r"(r[1]), "=r"(r[2]), "=r"(r[3]) : "r"(addr));
}
__device__ __forceinline__ void mma_f16(float* c, const uint32_t* a, const uint32_t* b) {
    asm volatile(
        "mma.sync.aligned.m16n8k16.row.col.f32.f16.f16.f32 "
        "{%0,%1,%2,%3},{%4,%5,%6,%7},{%8,%9},{%0,%1,%2,%3};"
        : "+f"(c[0]), "+f"(c[1]), "+f"(c[2]), "+f"(c[3])
        : "r"(a[0]), "r"(a[1]), "r"(a[2]), "r"(a[3]), "r"(b[0]), "r"(b[1]));
}

// ---------------------------------------------------------------------------
// coeff transpose: coeff[o,i,k] f32 -> g_C[k][o][i] f16   (1 MB one-shot)
// ---------------------------------------------------------------------------
__global__ void __launch_bounds__(256) ctrans_kernel(const float* __restrict__ coeff) {
    const int k = blockIdx.x;
    for (int idx = threadIdx.x; idx < 4096; idx += 256)
        g_C[k * 4096 + idx] = __float2half_rn(coeff[(size_t)idx * 64 + k]);
}

// ---------------------------------------------------------------------------
// W transpose + fp16: W[(k,e)][d] f32 -> g_B[d][(k,e)] f16
// ---------------------------------------------------------------------------
__global__ void __launch_bounds__(256) wsplit_kernel(const float* __restrict__ W) {
    __shared__ float s[32][33];
    const int kb = blockIdx.x;      // k-flat / 32
    const int nb = blockIdx.y;      // d / 32
    const int tx = threadIdx.x & 31, tg = threadIdx.x >> 5;

#pragma unroll
    for (int r = 0; r < 4; ++r) {
        int kr = tg + r * 8;
        s[kr][tx] = W[(size_t)(kb * 32 + kr) * DD + nb * 32 + tx];
    }
    __syncthreads();
#pragma unroll
    for (int r = 0; r < 4; ++r) {
        int nr = tg + r * 8;
        g_B[(size_t)(nb * 32 + nr) * KTOT + kb * 32 + tx] = __float2half_rn(s[tx][nr]);
    }
}

// ---------------------------------------------------------------------------
// Stage 1 (tensorized): T[b*64+o][k*512+e] = sum_i coeff[o,i,k]*x[b,i,e] -> f16
// CTA: (k-group of 8, b). 8 warps, warp = one k: 64x512x64 fp16 MMA.
// sX[e][i] f16 swizzled (SW128 rows of 128B), sC[k][o][i] per warp.
// ---------------------------------------------------------------------------
__global__ void __launch_bounds__(256, 1) stage1_mma_kernel(const float* __restrict__ x) {
    extern __shared__ char smem[];
    const uint32_t sb  = smem_u32(smem);
    const uint32_t sxb = sb;            // 65536 B
    const uint32_t scb = sb + 65536;    // 65536 B
    const int tid = threadIdx.x, lane = tid & 31, wid = tid >> 5;
    const int k = blockIdx.x * 8 + wid;
    const int b = blockIdx.y;

    // ---- load x[b] (f32) -> sX[e][i] f16, swizzled ----
    const float* xb = x + (size_t)b * 64 * 512;
#pragma unroll 4
    for (int n = 0; n < 32; ++n) {
        int g = n * 256 + tid;
        int i = g >> 7, e = (g & 127) * 4;
        float4 v = *(const float4*)&xb[i * 512 + e];
        __half h[4] = {__float2half_rn(v.x), __float2half_rn(v.y),
                       __float2half_rn(v.z), __float2half_rn(v.w)};
#pragma unroll
        for (int j = 0; j < 4; ++j) {
            uint32_t off = (e + j) * 128 + ((i * 2) ^ (((e + j) & 7) * 16));
            *(__half*)(smem + off) = h[j];
        }
    }
    // ---- load g_C[k] -> sC[wid][o][i], swizzled (coalesced int4) ----
    {
        const __half* gc = g_C + (size_t)k * 4096;
#pragma unroll
        for (int n = 0; n < 16; ++n) {
            int idx = n * 32 + lane;
            int o = idx >> 3, c8 = idx & 7;
            uint32_t off = 65536 + wid * 8192 + o * 128 + ((c8 * 16) ^ ((o & 7) * 16));
            *(int4*)(smem + off) = *(const int4*)(gc + o * 64 + c8 * 8);
        }
    }
    __syncthreads();

    // ---- ldmatrix lane geometry ----
    const int a_row  = (lane & 7) | (((lane >> 3) & 1) << 3);
    const int a_k16b = (lane >> 4) * 16;
    const int b_nr   = (lane & 7) | (((lane >> 4) & 1) << 3);
    const int b_k16b = ((lane >> 3) & 1) * 16;

    // ---- preload A-fragments (coeff_k), 4 o-tiles x 4 i16-steps ----
    uint32_t a[4][4][4];
#pragma unroll
    for (int ot = 0; ot < 4; ++ot)
#pragma unroll
        for (int k16 = 0; k16 < 4; ++k16) {
            int r = ot * 16 + a_row;
            uint32_t off = scb + wid * 8192 + r * 128 + ((k16 * 32 + a_k16b) ^ ((r & 7) * 16));
            ldsm4(a[ot][k16], off);
        }

    __half* gOut = g_A + (size_t)(b * 64) * KTOT + (size_t)k * 512;

#pragma unroll 1
    for (int et = 0; et < 16; ++et) {     // e-tiles of 32
        float acc[4][4][4];
#pragma unroll
        for (int ot = 0; ot < 4; ++ot)
#pragma unroll
            for (int nt = 0; nt < 4; ++nt)
#pragma unroll
                for (int j = 0; j < 4; ++j) acc[ot][nt][j] = 0.0f;

#pragma unroll
        for (int k16 = 0; k16 < 4; ++k16) {
            uint32_t bb[2][4];
#pragma unroll
            for (int p = 0; p < 2; ++p) {
                int nrow = et * 32 + p * 16 + b_nr;
                uint32_t off = sxb + nrow * 128 + ((k16 * 32 + b_k16b) ^ ((nrow & 7) * 16));
                ldsm4(bb[p], off);
            }
#pragma unroll
            for (int ot = 0; ot < 4; ++ot)
#pragma unroll
                for (int nt = 0; nt < 4; ++nt)
                    mma_f16(acc[ot][nt], a[ot][k16], &bb[nt >> 1][(nt & 1) * 2]);
        }
        // store fp16
#pragma unroll
        for (int ot = 0; ot < 4; ++ot)
#pragma unroll
            for (int nt = 0; nt < 4; ++nt) {
                int o = ot * 16 + (lane >> 2);
                int e = et * 32 + nt * 8 + (lane & 3) * 2;
                *(__half2*)&gOut[(size_t)o * KTOT + e] =
                    __floats2half2_rn(acc[ot][nt][0], acc[ot][nt][1]);
                *(__half2*)&gOut[(size_t)(o + 8) * KTOT + e] =
                    __floats2half2_rn(acc[ot][nt][2], acc[ot][nt][3]);
            }
    }
}

// ---------------------------------------------------------------------------
// Stage 2: fp16 single-term split-K GEMM:  part += A * B
// CTA 128x256, BK=64, 8 warps (64x64 warp tile), 3-stage cp.async, SW128 smem.
// grid (2, 16, SPLIT) = 128 CTAs.
// ---------------------------------------------------------------------------
__global__ void __launch_bounds__(256, 1) gemm_kernel() {
    extern __shared__ char smem[];
    const uint32_t sb = (smem_u32(smem) + 1023) & ~1023u;

    const int tid  = threadIdx.x;
    const int lane = tid & 31;
    const int wid  = tid >> 5;
    const int n0 = blockIdx.x * BN;
    const int m0 = blockIdx.y * BM;
    const size_t k0 = (size_t)blockIdx.z * KPER;
    const int warp_m = (wid >> 2) * 64;
    const int warp_n = (wid & 3) * 64;

    const int ar  = tid >> 1;
    const int ac0 = (tid & 1) * 4;
    const __half* gA = g_A + (size_t)(m0 + ar) * KTOT + k0;
    const __half* gB = g_B + (size_t)(n0 + tid) * KTOT + k0;

    uint32_t aswz[4], bswz[8];
#pragma unroll
    for (int j = 0; j < 4; ++j)
        aswz[j] = ar * 128 + (((ac0 + j) * 16) ^ ((ar & 7) * 16));
#pragma unroll
    for (int j = 0; j < 8; ++j)
        bswz[j] = tid * 128 + ((j * 16) ^ ((tid & 7) * 16));

    const int a_row  = (lane & 7) | (((lane >> 3) & 1) << 3);
    const int a_k16b = (lane >> 4) * 16;
    const int b_nr   = (lane & 7) | (((lane >> 4) & 1) << 3);
    const int b_k16b = ((lane >> 3) & 1) * 16;

    float acc[4][8][4];
#pragma unroll
    for (int mt = 0; mt < 4; ++mt)
#pragma unroll
        for (int nt = 0; nt < 8; ++nt)
#pragma unroll
            for (int j = 0; j < 4; ++j) acc[mt][nt][j] = 0.0f;

    auto load_stage = [&](int c, int s) {
        const uint32_t base = sb + s * STAGE_BYTES;
        const int ke = c * BK;
#pragma unroll
        for (int j = 0; j < 4; ++j)
            cp16(base + aswz[j], gA + ke + (ac0 + j) * 8);
#pragma unroll
        for (int j = 0; j < 8; ++j)
            cp16(base + 16384 + bswz[j], gB + ke + j * 8);
        CP_COMMIT();
    };

    load_stage(0, 0);
    load_stage(1, 1);

    int s = 0;
    for (int c = 0; c < NCH; ++c) {
        if (c + 2 < NCH)      { load_stage(c + 2, (c + 2) % NSTG); CP_WAIT(2); }
        else if (c + 1 < NCH) { CP_WAIT(1); }
        else                  { CP_WAIT(0); }
        __syncthreads();

        const uint32_t Ab = sb + s * STAGE_BYTES;
        const uint32_t Bb = Ab + 16384;

#pragma unroll
        for (int k16 = 0; k16 < 4; ++k16) {
            uint32_t a[4][4], bh[4][4];
#pragma unroll
            for (int mt = 0; mt < 4; ++mt) {
                int r = warp_m + mt * 16 + a_row;
                uint32_t off = r * 128 + ((k16 * 32 + a_k16b) ^ ((r & 7) * 16));
                ldsm4(a[mt], Ab + off);
            }
#pragma unroll
            for (int p = 0; p < 4; ++p) {
                int n = warp_n + p * 16 + b_nr;
                uint32_t off = n * 128 + ((k16 * 32 + b_k16b) ^ ((n & 7) * 16));
                ldsm4(bh[p], Bb + off);
            }
#pragma unroll
            for (int mt = 0; mt < 4; ++mt)
#pragma unroll
                for (int nt = 0; nt < 8; ++nt)
                    mma_f16(acc[mt][nt], a[mt], &bh[nt >> 1][(nt & 1) * 2]);
        }
        __syncthreads();
        s = (s + 1 == NSTG) ? 0 : s + 1;
    }

    float* Cp = g_part + (size_t)blockIdx.z * MM * DD;
#pragma unroll
    for (int mt = 0; mt < 4; ++mt)
#pragma unroll
        for (int nt = 0; nt < 8; ++nt) {
            int r    = m0 + warp_m + mt * 16 + (lane >> 2);
            int ccol = n0 + warp_n + nt * 8 + (lane & 3) * 2;
            *(float2*)&Cp[(size_t)r * DD + ccol] =
                make_float2(acc[mt][nt][0], acc[mt][nt][1]);
            *(float2*)&Cp[(size_t)(r + 8) * DD + ccol] =
                make_float2(acc[mt][nt][2], acc[mt][nt][3]);
        }
}

// ---------------------------------------------------------------------------
// Reduce split-K partials
// ---------------------------------------------------------------------------
__global__ void __launch_bounds__(256) reduce_kernel(float* __restrict__ out) {
    const int idx = blockIdx.x * 256 + threadIdx.x;
    const float4* p = (const float4*)g_part;
    float4 s = p[idx];
#pragma unroll
    for (int sp = 1; sp < SPLIT; ++sp) {
        float4 v = p[(size_t)sp * (MM * DD / 4) + idx];
        s.x += v.x; s.y += v.y; s.z += v.z; s.w += v.w;
    }
    ((float4*)out)[idx] = s;
}

extern "C" void kernel_launch(void* const* d_in, const int* in_sizes, int n_in,
                              void* d_out, int out_size) {
    const float* x     = (const float*)d_in[0];  // [32,64,512]
    const float* w     = (const float*)d_in[1];  // [64,512,512]
    const float* coeff = (const float*)d_in[2];  // [64,64,64]
    float* out = (float*)d_out;                  // [32,64,512]

    cudaFuncSetAttribute(gemm_kernel,       cudaFuncAttributeMaxDynamicSharedMemorySize, GEMM_SMEM);
    cudaFuncSetAttribute(stage1_mma_kernel, cudaFuncAttributeMaxDynamicSharedMemorySize, S1_SMEM);

    ctrans_kernel<<<KK, 256>>>(coeff);
    wsplit_kernel<<<dim3(KTOT / 32, DD / 32), 256>>>(w);
    stage1_mma_kernel<<<dim3(KK / 8, B_), 256, S1_SMEM>>>(x);
    gemm_kernel<<<dim3(DD / BN, MM / BM, SPLIT), 256, GEMM_SMEM>>>();
    reduce_kernel<<<(MM * DD / 4) / 256, 256>>>(out);
}

// round 7
// speedup vs baseline: 4.4644x; 1.0086x over previous
#include <cuda_runtime.h>
#include <cuda_fp16.h>
#include <cstdint>

// ---------------- problem constants ----------------
#define B_    32
#define DD    512
#define KK    64
#define KTOT  32768            // K*D : flattened reduction dim
#define MM    2048             // B*F_out
#define SPLIT 4
#define KPER  (KTOT / SPLIT)   // 8192
#define BK    64               // k elems per pipeline stage (128 B rows)
#define NCH   (KPER / BK)      // 128
#define BM    128
#define BN    256
#define NSTG  3
#define STAGE_BYTES 49152      // A 16K + B 32K
#define GEMM_SMEM   (NSTG * STAGE_BYTES + 1024)
#define S1_SMEM     131072     // sX 64K + sC 64K

// ---------------- device scratch (no allocation) ----------------
__device__ __half g_A[(size_t)MM * KTOT];          // 128 MB (fp16 T)
__device__ __half g_B[(size_t)DD * KTOT];          // 32 MB  (W^T fp16)
__device__ __half g_C[(size_t)KK * 64 * 64];       // 512 KB (coeff [k][o][i] fp16)
__device__ float  g_part[(size_t)SPLIT * MM * DD]; // 16 MB

// ---------------- helpers ----------------
__device__ __forceinline__ uint32_t smem_u32(const void* p) {
    uint32_t a;
    asm("{ .reg .u64 t; cvta.to.shared.u64 t, %1; cvt.u32.u64 %0, t; }" : "=r"(a) : "l"(p));
    return a;
}
__device__ __forceinline__ void cp16(uint32_t dst, const void* src) {
    asm volatile("cp.async.cg.shared.global [%0], [%1], 16;" :: "r"(dst), "l"(src));
}
#define CP_COMMIT() asm volatile("cp.async.commit_group;" ::: "memory")
#define CP_WAIT(n)  asm volatile("cp.async.wait_group %0;" :: "n"(n) : "memory")

__device__ __forceinline__ void ldsm4(uint32_t* r, uint32_t addr) {
    asm volatile("ldmatrix.sync.aligned.m8n8.x4.shared.b16 {%0,%1,%2,%3}, [%4];"
                 : "=r"(r[0]), "=r"(r[1]), "=r"(r[2]), "=r"(r[3]) : "r"(addr));
}
__device__ __forceinline__ void mma_f16(float* c, const uint32_t* a, const uint32_t* b) {
    asm volatile(
        "mma.sync.aligned.m16n8k16.row.col.f32.f16.f16.f32 "
        "{%0,%1,%2,%3},{%4,%5,%6,%7},{%8,%9},{%0,%1,%2,%3};"
        : "+f"(c[0]), "+f"(c[1]), "+f"(c[2]), "+f"(c[3])
        : "r"(a[0]), "r"(a[1]), "r"(a[2]), "r"(a[3]), "r"(b[0]), "r"(b[1]));
}

// ---------------------------------------------------------------------------
// coeff transpose: coeff[o,i,k] f32 -> g_C[k][o][i] f16
// ---------------------------------------------------------------------------
__global__ void __launch_bounds__(256) ctrans_kernel(const float* __restrict__ coeff) {
    const int k = blockIdx.x;
    for (int idx = threadIdx.x; idx < 4096; idx += 256)
        g_C[k * 4096 + idx] = __float2half_rn(coeff[(size_t)idx * 64 + k]);
}

// ---------------------------------------------------------------------------
// W transpose + fp16: W[(k,e)][d] f32 -> g_B[d][(k,e)] f16
// ---------------------------------------------------------------------------
__global__ void __launch_bounds__(256) wsplit_kernel(const float* __restrict__ W) {
    __shared__ float s[32][33];
    const int kb = blockIdx.x;
    const int nb = blockIdx.y;
    const int tx = threadIdx.x & 31, tg = threadIdx.x >> 5;

#pragma unroll
    for (int r = 0; r < 4; ++r) {
        int kr = tg + r * 8;
        s[kr][tx] = W[(size_t)(kb * 32 + kr) * DD + nb * 32 + tx];
    }
    __syncthreads();
#pragma unroll
    for (int r = 0; r < 4; ++r) {
        int nr = tg + r * 8;
        g_B[(size_t)(nb * 32 + nr) * KTOT + kb * 32 + tx] = __float2half_rn(s[tx][nr]);
    }
}

// ---------------------------------------------------------------------------
// Stage 1 (tensorized): T[b*64+o][k*512+e] = sum_i coeff[o,i,k]*x[b,i,e] -> f16
// ---------------------------------------------------------------------------
__global__ void __launch_bounds__(256, 1) stage1_mma_kernel(const float* __restrict__ x) {
    extern __shared__ char smem[];
    const uint32_t sb  = smem_u32(smem);
    const uint32_t sxb = sb;
    const uint32_t scb = sb + 65536;
    const int tid = threadIdx.x, lane = tid & 31, wid = tid >> 5;
    const int k = blockIdx.x * 8 + wid;
    const int b = blockIdx.y;

    const float* xb = x + (size_t)b * 64 * 512;
#pragma unroll 4
    for (int n = 0; n < 32; ++n) {
        int g = n * 256 + tid;
        int i = g >> 7, e = (g & 127) * 4;
        float4 v = *(const float4*)&xb[i * 512 + e];
        __half h[4] = {__float2half_rn(v.x), __float2half_rn(v.y),
                       __float2half_rn(v.z), __float2half_rn(v.w)};
#pragma unroll
        for (int j = 0; j < 4; ++j) {
            uint32_t off = (e + j) * 128 + ((i * 2) ^ (((e + j) & 7) * 16));
            *(__half*)(smem + off) = h[j];
        }
    }
    {
        const __half* gc = g_C + (size_t)k * 4096;
#pragma unroll
        for (int n = 0; n < 16; ++n) {
            int idx = n * 32 + lane;
            int o = idx >> 3, c8 = idx & 7;
            uint32_t off = 65536 + wid * 8192 + o * 128 + ((c8 * 16) ^ ((o & 7) * 16));
            *(int4*)(smem + off) = *(const int4*)(gc + o * 64 + c8 * 8);
        }
    }
    __syncthreads();

    const int a_row  = (lane & 7) | (((lane >> 3) & 1) << 3);
    const int a_k16b = (lane >> 4) * 16;
    const int b_nr   = (lane & 7) | (((lane >> 4) & 1) << 3);
    const int b_k16b = ((lane >> 3) & 1) * 16;

    uint32_t a[4][4][4];
#pragma unroll
    for (int ot = 0; ot < 4; ++ot)
#pragma unroll
        for (int k16 = 0; k16 < 4; ++k16) {
            int r = ot * 16 + a_row;
            uint32_t off = scb + wid * 8192 + r * 128 + ((k16 * 32 + a_k16b) ^ ((r & 7) * 16));
            ldsm4(a[ot][k16], off);
        }

    __half* gOut = g_A + (size_t)(b * 64) * KTOT + (size_t)k * 512;

#pragma unroll 1
    for (int et = 0; et < 16; ++et) {
        float acc[4][4][4];
#pragma unroll
        for (int ot = 0; ot < 4; ++ot)
#pragma unroll
            for (int nt = 0; nt < 4; ++nt)
#pragma unroll
                for (int j = 0; j < 4; ++j) acc[ot][nt][j] = 0.0f;

#pragma unroll
        for (int k16 = 0; k16 < 4; ++k16) {
            uint32_t bb[2][4];
#pragma unroll
            for (int p = 0; p < 2; ++p) {
                int nrow = et * 32 + p * 16 + b_nr;
                uint32_t off = sxb + nrow * 128 + ((k16 * 32 + b_k16b) ^ ((nrow & 7) * 16));
                ldsm4(bb[p], off);
            }
#pragma unroll
            for (int ot = 0; ot < 4; ++ot)
#pragma unroll
                for (int nt = 0; nt < 4; ++nt)
                    mma_f16(acc[ot][nt], a[ot][k16], &bb[nt >> 1][(nt & 1) * 2]);
        }
#pragma unroll
        for (int ot = 0; ot < 4; ++ot)
#pragma unroll
            for (int nt = 0; nt < 4; ++nt) {
                int o = ot * 16 + (lane >> 2);
                int e = et * 32 + nt * 8 + (lane & 3) * 2;
                *(__half2*)&gOut[(size_t)o * KTOT + e] =
                    __floats2half2_rn(acc[ot][nt][0], acc[ot][nt][1]);
                *(__half2*)&gOut[(size_t)(o + 8) * KTOT + e] =
                    __floats2half2_rn(acc[ot][nt][2], acc[ot][nt][3]);
            }
    }
}

// ---------------------------------------------------------------------------
// Stage 2: fp16 split-K GEMM, de-bubbled mainloop:
//  - single __syncthreads per chunk (wait -> sync -> issue next stage load)
//  - A fragments preloaded for whole chunk, B fragments double-buffered per k16
// ---------------------------------------------------------------------------
__global__ void __launch_bounds__(256, 1) gemm_kernel() {
    extern __shared__ char smem[];
    const uint32_t sb = (smem_u32(smem) + 1023) & ~1023u;

    const int tid  = threadIdx.x;
    const int lane = tid & 31;
    const int wid  = tid >> 5;
    const int n0 = blockIdx.x * BN;
    const int m0 = blockIdx.y * BM;
    const size_t k0 = (size_t)blockIdx.z * KPER;
    const int warp_m = (wid >> 2) * 64;
    const int warp_n = (wid & 3) * 64;

    const int ar  = tid >> 1;
    const int ac0 = (tid & 1) * 4;
    const __half* gA = g_A + (size_t)(m0 + ar) * KTOT + k0;
    const __half* gB = g_B + (size_t)(n0 + tid) * KTOT + k0;

    uint32_t aswz[4], bswz[8];
#pragma unroll
    for (int j = 0; j < 4; ++j)
        aswz[j] = ar * 128 + (((ac0 + j) * 16) ^ ((ar & 7) * 16));
#pragma unroll
    for (int j = 0; j < 8; ++j)
        bswz[j] = tid * 128 + ((j * 16) ^ ((tid & 7) * 16));

    const int a_row  = (lane & 7) | (((lane >> 3) & 1) << 3);
    const int a_k16b = (lane >> 4) * 16;
    const int b_nr   = (lane & 7) | (((lane >> 4) & 1) << 3);
    const int b_k16b = ((lane >> 3) & 1) * 16;

    // precomputed swizzled fragment offsets (relative to stage base)
    uint32_t aoff[4][4], boff[4][4];
#pragma unroll
    for (int mt = 0; mt < 4; ++mt)
#pragma unroll
        for (int k16 = 0; k16 < 4; ++k16) {
            int r = warp_m + mt * 16 + a_row;
            aoff[mt][k16] = r * 128 + ((k16 * 32 + a_k16b) ^ ((r & 7) * 16));
        }
#pragma unroll
    for (int p = 0; p < 4; ++p)
#pragma unroll
        for (int k16 = 0; k16 < 4; ++k16) {
            int n = warp_n + p * 16 + b_nr;
            boff[p][k16] = 16384 + n * 128 + ((k16 * 32 + b_k16b) ^ ((n & 7) * 16));
        }

    float acc[4][8][4];
#pragma unroll
    for (int mt = 0; mt < 4; ++mt)
#pragma unroll
        for (int nt = 0; nt < 8; ++nt)
#pragma unroll
            for (int j = 0; j < 4; ++j) acc[mt][nt][j] = 0.0f;

    auto load_stage = [&](int c, int s) {
        const uint32_t base = sb + s * STAGE_BYTES;
        const int ke = c * BK;
#pragma unroll
        for (int j = 0; j < 4; ++j)
            cp16(base + aswz[j], gA + ke + (ac0 + j) * 8);
#pragma unroll
        for (int j = 0; j < 8; ++j)
            cp16(base + 16384 + bswz[j], gB + ke + j * 8);
        CP_COMMIT();
    };

    load_stage(0, 0);
    load_stage(1, 1);

    int s = 0;
    for (int c = 0; c < NCH; ++c) {
        if (c + 1 < NCH) { CP_WAIT(1); } else { CP_WAIT(0); }
        __syncthreads();
        if (c + 2 < NCH) load_stage(c + 2, (c + 2) % NSTG);

        const uint32_t Sb = sb + s * STAGE_BYTES;

        // preload all A fragments for the chunk
        uint32_t a[4][4][4];   // [k16][mt][4]
#pragma unroll
        for (int k16 = 0; k16 < 4; ++k16)
#pragma unroll
            for (int mt = 0; mt < 4; ++mt)
                ldsm4(a[k16][mt], Sb + aoff[mt][k16]);

        // B double-buffered across k16
        uint32_t bb[2][4][4];
#pragma unroll
        for (int p = 0; p < 4; ++p)
            ldsm4(bb[0][p], Sb + boff[p][0]);

#pragma unroll
        for (int k16 = 0; k16 < 4; ++k16) {
            if (k16 < 3) {
#pragma unroll
                for (int p = 0; p < 4; ++p)
                    ldsm4(bb[(k16 + 1) & 1][p], Sb + boff[p][k16 + 1]);
            }
            const int cur = k16 & 1;
#pragma unroll
            for (int mt = 0; mt < 4; ++mt)
#pragma unroll
                for (int nt = 0; nt < 8; ++nt)
                    mma_f16(acc[mt][nt], a[k16][mt], &bb[cur][nt >> 1][(nt & 1) * 2]);
        }
        s = (s + 1 == NSTG) ? 0 : s + 1;
    }

    float* Cp = g_part + (size_t)blockIdx.z * MM * DD;
#pragma unroll
    for (int mt = 0; mt < 4; ++mt)
#pragma unroll
        for (int nt = 0; nt < 8; ++nt) {
            int r    = m0 + warp_m + mt * 16 + (lane >> 2);
            int ccol = n0 + warp_n + nt * 8 + (lane & 3) * 2;
            *(float2*)&Cp[(size_t)r * DD + ccol] =
                make_float2(acc[mt][nt][0], acc[mt][nt][1]);
            *(float2*)&Cp[(size_t)(r + 8) * DD + ccol] =
                make_float2(acc[mt][nt][2], acc[mt][nt][3]);
        }
}

// ---------------------------------------------------------------------------
// Reduce split-K partials
// ---------------------------------------------------------------------------
__global__ void __launch_bounds__(256) reduce_kernel(float* __restrict__ out) {
    const int idx = blockIdx.x * 256 + threadIdx.x;
    const float4* p = (const float4*)g_part;
    float4 s = p[idx];
#pragma unroll
    for (int sp = 1; sp < SPLIT; ++sp) {
        float4 v = p[(size_t)sp * (MM * DD / 4) + idx];
        s.x += v.x; s.y += v.y; s.z += v.z; s.w += v.w;
    }
    ((float4*)out)[idx] = s;
}

extern "C" void kernel_launch(void* const* d_in, const int* in_sizes, int n_in,
                              void* d_out, int out_size) {
    const float* x     = (const float*)d_in[0];  // [32,64,512]
    const float* w     = (const float*)d_in[1];  // [64,512,512]
    const float* coeff = (const float*)d_in[2];  // [64,64,64]
    float* out = (float*)d_out;                  // [32,64,512]

    cudaFuncSetAttribute(gemm_kernel,       cudaFuncAttributeMaxDynamicSharedMemorySize, GEMM_SMEM);
    cudaFuncSetAttribute(stage1_mma_kernel, cudaFuncAttributeMaxDynamicSharedMemorySize, S1_SMEM);

    ctrans_kernel<<<KK, 256>>>(coeff);
    wsplit_kernel<<<dim3(KTOT / 32, DD / 32), 256>>>(w);
    stage1_mma_kernel<<<dim3(KK / 8, B_), 256, S1_SMEM>>>(x);
    gemm_kernel<<<dim3(DD / BN, MM / BM, SPLIT), 256, GEMM_SMEM>>>();
    reduce_kernel<<<(MM * DD / 4) / 256, 256>>>(out);
}

// round 8
// speedup vs baseline: 5.2054x; 1.1660x over previous
#include <cuda_runtime.h>
#include <cuda_fp16.h>
#include <cstdint>

// ---------------- problem constants ----------------
#define B_    32
#define DD    512
#define KK    64
#define KTOT  32768            // K*D : flattened reduction dim
#define MM    2048             // B*F_out
#define SPLIT 4
#define KPER  (KTOT / SPLIT)   // 8192
#define BK    64               // k elems per pipeline stage (128 B rows)
#define NCH   (KPER / BK)      // 128
#define BM    128
#define BN    128
#define NSTG  3
#define STAGE_BYTES 32768      // A 16K + B 16K
#define GEMM_SMEM   (NSTG * STAGE_BYTES + 1024)
#define S1_SMEM     131072     // sX 64K + sC 64K

// ---------------- device scratch (no allocation) ----------------
__device__ __half g_A[(size_t)MM * KTOT];          // 128 MB (fp16 T)
__device__ __half g_B[(size_t)DD * KTOT];          // 32 MB  (W^T fp16)
__device__ __half g_C[(size_t)KK * 64 * 64];       // 512 KB (coeff [k][o][i] fp16)
__device__ float  g_part[(size_t)SPLIT * MM * DD]; // 16 MB

// ---------------- helpers ----------------
__device__ __forceinline__ uint32_t smem_u32(const void* p) {
    uint32_t a;
    asm("{ .reg .u64 t; cvta.to.shared.u64 t, %1; cvt.u32.u64 %0, t; }" : "=r"(a) : "l"(p));
    return a;
}
__device__ __forceinline__ void cp16(uint32_t dst, const void* src) {
    asm volatile("cp.async.cg.shared.global [%0], [%1], 16;" :: "r"(dst), "l"(src));
}
#define CP_COMMIT() asm volatile("cp.async.commit_group;" ::: "memory")
#define CP_WAIT(n)  asm volatile("cp.async.wait_group %0;" :: "n"(n) : "memory")

__device__ __forceinline__ void ldsm4(uint32_t* r, uint32_t addr) {
    asm volatile("ldmatrix.sync.aligned.m8n8.x4.shared.b16 {%0,%1,%2,%3}, [%4];"
                 : "=r"(r[0]), "=r"(r[1]), "=r"(r[2]), "=r"(r[3]) : "r"(addr));
}
__device__ __forceinline__ void mma_f16(float* c, const uint32_t* a, const uint32_t* b) {
    asm volatile(
        "mma.sync.aligned.m16n8k16.row.col.f32.f16.f16.f32 "
        "{%0,%1,%2,%3},{%4,%5,%6,%7},{%8,%9},{%0,%1,%2,%3};"
        : "+f"(c[0]), "+f"(c[1]), "+f"(c[2]), "+f"(c[3])
        : "r"(a[0]), "r"(a[1]), "r"(a[2]), "r"(a[3]), "r"(b[0]), "r"(b[1]));
}

// ---------------------------------------------------------------------------
// coeff transpose: coeff[o,i,k] f32 -> g_C[k][o][i] f16
// ---------------------------------------------------------------------------
__global__ void __launch_bounds__(256) ctrans_kernel(const float* __restrict__ coeff) {
    const int k = blockIdx.x;
    for (int idx = threadIdx.x; idx < 4096; idx += 256)
        g_C[k * 4096 + idx] = __float2half_rn(coeff[(size_t)idx * 64 + k]);
}

// ---------------------------------------------------------------------------
// W transpose + fp16: W[(k,e)][d] f32 -> g_B[d][(k,e)] f16
// ---------------------------------------------------------------------------
__global__ void __launch_bounds__(256) wsplit_kernel(const float* __restrict__ W) {
    __shared__ float s[32][33];
    const int kb = blockIdx.x;
    const int nb = blockIdx.y;
    const int tx = threadIdx.x & 31, tg = threadIdx.x >> 5;

#pragma unroll
    for (int r = 0; r < 4; ++r) {
        int kr = tg + r * 8;
        s[kr][tx] = W[(size_t)(kb * 32 + kr) * DD + nb * 32 + tx];
    }
    __syncthreads();
#pragma unroll
    for (int r = 0; r < 4; ++r) {
        int nr = tg + r * 8;
        g_B[(size_t)(nb * 32 + nr) * KTOT + kb * 32 + tx] = __float2half_rn(s[tx][nr]);
    }
}

// ---------------------------------------------------------------------------
// Stage 1 (tensorized): T[b*64+o][k*512+e] = sum_i coeff[o,i,k]*x[b,i,e] -> f16
// ---------------------------------------------------------------------------
__global__ void __launch_bounds__(256, 1) stage1_mma_kernel(const float* __restrict__ x) {
    extern __shared__ char smem[];
    const uint32_t sb  = smem_u32(smem);
    const uint32_t sxb = sb;
    const uint32_t scb = sb + 65536;
    const int tid = threadIdx.x, lane = tid & 31, wid = tid >> 5;
    const int k = blockIdx.x * 8 + wid;
    const int b = blockIdx.y;

    const float* xb = x + (size_t)b * 64 * 512;
#pragma unroll 4
    for (int n = 0; n < 32; ++n) {
        int g = n * 256 + tid;
        int i = g >> 7, e = (g & 127) * 4;
        float4 v = *(const float4*)&xb[i * 512 + e];
        __half h[4] = {__float2half_rn(v.x), __float2half_rn(v.y),
                       __float2half_rn(v.z), __float2half_rn(v.w)};
#pragma unroll
        for (int j = 0; j < 4; ++j) {
            uint32_t off = (e + j) * 128 + ((i * 2) ^ (((e + j) & 7) * 16));
            *(__half*)(smem + off) = h[j];
        }
    }
    {
        const __half* gc = g_C + (size_t)k * 4096;
#pragma unroll
        for (int n = 0; n < 16; ++n) {
            int idx = n * 32 + lane;
            int o = idx >> 3, c8 = idx & 7;
            uint32_t off = 65536 + wid * 8192 + o * 128 + ((c8 * 16) ^ ((o & 7) * 16));
            *(int4*)(smem + off) = *(const int4*)(gc + o * 64 + c8 * 8);
        }
    }
    __syncthreads();

    const int a_row  = (lane & 7) | (((lane >> 3) & 1) << 3);
    const int a_k16b = (lane >> 4) * 16;
    const int b_nr   = (lane & 7) | (((lane >> 4) & 1) << 3);
    const int b_k16b = ((lane >> 3) & 1) * 16;

    uint32_t a[4][4][4];
#pragma unroll
    for (int ot = 0; ot < 4; ++ot)
#pragma unroll
        for (int k16 = 0; k16 < 4; ++k16) {
            int r = ot * 16 + a_row;
            uint32_t off = scb + wid * 8192 + r * 128 + ((k16 * 32 + a_k16b) ^ ((r & 7) * 16));
            ldsm4(a[ot][k16], off);
        }

    __half* gOut = g_A + (size_t)(b * 64) * KTOT + (size_t)k * 512;

#pragma unroll 1
    for (int et = 0; et < 16; ++et) {
        float acc[4][4][4];
#pragma unroll
        for (int ot = 0; ot < 4; ++ot)
#pragma unroll
            for (int nt = 0; nt < 4; ++nt)
#pragma unroll
                for (int j = 0; j < 4; ++j) acc[ot][nt][j] = 0.0f;

#pragma unroll
        for (int k16 = 0; k16 < 4; ++k16) {
            uint32_t bb[2][4];
#pragma unroll
            for (int p = 0; p < 2; ++p) {
                int nrow = et * 32 + p * 16 + b_nr;
                uint32_t off = sxb + nrow * 128 + ((k16 * 32 + b_k16b) ^ ((nrow & 7) * 16));
                ldsm4(bb[p], off);
            }
#pragma unroll
            for (int ot = 0; ot < 4; ++ot)
#pragma unroll
                for (int nt = 0; nt < 4; ++nt)
                    mma_f16(acc[ot][nt], a[ot][k16], &bb[nt >> 1][(nt & 1) * 2]);
        }
#pragma unroll
        for (int ot = 0; ot < 4; ++ot)
#pragma unroll
            for (int nt = 0; nt < 4; ++nt) {
                int o = ot * 16 + (lane >> 2);
                int e = et * 32 + nt * 8 + (lane & 3) * 2;
                *(__half2*)&gOut[(size_t)o * KTOT + e] =
                    __floats2half2_rn(acc[ot][nt][0], acc[ot][nt][1]);
                *(__half2*)&gOut[(size_t)(o + 8) * KTOT + e] =
                    __floats2half2_rn(acc[ot][nt][2], acc[ot][nt][3]);
            }
    }
}

// ---------------------------------------------------------------------------
// Stage 2: fp16 split-K GEMM, occupancy-oriented:
//  CTA 128x128, 256 threads, warp tile 64x32 (2m x 4n warps), 3-stage pipeline.
//  2 CTAs/SM (regs ~120, smem 97KB) -> 16 warps/SM to hide LDSM/MMA latency.
//  grid (4, 16, SPLIT) = 256 CTAs.
// ---------------------------------------------------------------------------
__global__ void __launch_bounds__(256, 2) gemm_kernel() {
    extern __shared__ char smem[];
    const uint32_t sb = smem_u32(smem);

    const int tid  = threadIdx.x;
    const int lane = tid & 31;
    const int wid  = tid >> 5;
    const int n0 = blockIdx.x * BN;
    const int m0 = blockIdx.y * BM;
    const size_t k0 = (size_t)blockIdx.z * KPER;
    const int warp_m = (wid & 1) * 64;
    const int warp_n = (wid >> 1) * 32;

    // ---- cp.async: A & B each 128 rows x 128B per stage ----
    const int r2  = tid >> 1;          // row 0..127
    const int c0  = (tid & 1) * 4;     // 16B-chunk base
    const __half* gA = g_A + (size_t)(m0 + r2) * KTOT + k0 + c0 * 8;
    const __half* gB = g_B + (size_t)(n0 + r2) * KTOT + k0 + c0 * 8;

    uint32_t swz[4];
#pragma unroll
    for (int j = 0; j < 4; ++j)
        swz[j] = r2 * 128 + (((c0 + j) * 16) ^ ((r2 & 7) * 16));

    const int a_row  = (lane & 7) | (((lane >> 3) & 1) << 3);
    const int a_k16b = (lane >> 4) * 16;
    const int b_nr   = (lane & 7) | (((lane >> 4) & 1) << 3);
    const int b_k16b = ((lane >> 3) & 1) * 16;

    float acc[4][4][4];
#pragma unroll
    for (int mt = 0; mt < 4; ++mt)
#pragma unroll
        for (int nt = 0; nt < 4; ++nt)
#pragma unroll
            for (int j = 0; j < 4; ++j) acc[mt][nt][j] = 0.0f;

    auto load_stage = [&](int c, int s) {
        const uint32_t base = sb + s * STAGE_BYTES;
        const int ke = c * BK;
#pragma unroll
        for (int j = 0; j < 4; ++j) {
            cp16(base + swz[j],         gA + ke + j * 8);
            cp16(base + 16384 + swz[j], gB + ke + j * 8);
        }
        CP_COMMIT();
    };

    load_stage(0, 0);
    load_stage(1, 1);

    int s = 0;
    for (int c = 0; c < NCH; ++c) {
        if (c + 1 < NCH) { CP_WAIT(1); } else { CP_WAIT(0); }
        __syncthreads();
        if (c + 2 < NCH) load_stage(c + 2, (c + 2) % NSTG);

        const uint32_t Ab = sb + s * STAGE_BYTES;
        const uint32_t Bb = Ab + 16384;

#pragma unroll
        for (int k16 = 0; k16 < 4; ++k16) {
            uint32_t a[4][4], bb[2][4];
#pragma unroll
            for (int mt = 0; mt < 4; ++mt) {
                int r = warp_m + mt * 16 + a_row;
                ldsm4(a[mt], Ab + r * 128 + ((k16 * 32 + a_k16b) ^ ((r & 7) * 16)));
            }
#pragma unroll
            for (int p = 0; p < 2; ++p) {
                int n = warp_n + p * 16 + b_nr;
                ldsm4(bb[p], Bb + n * 128 + ((k16 * 32 + b_k16b) ^ ((n & 7) * 16)));
            }
#pragma unroll
            for (int mt = 0; mt < 4; ++mt)
#pragma unroll
                for (int nt = 0; nt < 4; ++nt)
                    mma_f16(acc[mt][nt], a[mt], &bb[nt >> 1][(nt & 1) * 2]);
        }
        s = (s + 1 == NSTG) ? 0 : s + 1;
    }

    float* Cp = g_part + (size_t)blockIdx.z * MM * DD;
#pragma unroll
    for (int mt = 0; mt < 4; ++mt)
#pragma unroll
        for (int nt = 0; nt < 4; ++nt) {
            int r    = m0 + warp_m + mt * 16 + (lane >> 2);
            int ccol = n0 + warp_n + nt * 8 + (lane & 3) * 2;
            *(float2*)&Cp[(size_t)r * DD + ccol] =
                make_float2(acc[mt][nt][0], acc[mt][nt][1]);
            *(float2*)&Cp[(size_t)(r + 8) * DD + ccol] =
                make_float2(acc[mt][nt][2], acc[mt][nt][3]);
        }
}

// ---------------------------------------------------------------------------
// Reduce split-K partials
// ---------------------------------------------------------------------------
__global__ void __launch_bounds__(256) reduce_kernel(float* __restrict__ out) {
    const int idx = blockIdx.x * 256 + threadIdx.x;
    const float4* p = (const float4*)g_part;
    float4 s = p[idx];
#pragma unroll
    for (int sp = 1; sp < SPLIT; ++sp) {
        float4 v = p[(size_t)sp * (MM * DD / 4) + idx];
        s.x += v.x; s.y += v.y; s.z += v.z; s.w += v.w;
    }
    ((float4*)out)[idx] = s;
}

extern "C" void kernel_launch(void* const* d_in, const int* in_sizes, int n_in,
                              void* d_out, int out_size) {
    const float* x     = (const float*)d_in[0];  // [32,64,512]
    const float* w     = (const float*)d_in[1];  // [64,512,512]
    const float* coeff = (const float*)d_in[2];  // [64,64,64]
    float* out = (float*)d_out;                  // [32,64,512]

    cudaFuncSetAttribute(gemm_kernel,       cudaFuncAttributeMaxDynamicSharedMemorySize, GEMM_SMEM);
    cudaFuncSetAttribute(stage1_mma_kernel, cudaFuncAttributeMaxDynamicSharedMemorySize, S1_SMEM);

    ctrans_kernel<<<KK, 256>>>(coeff);
    wsplit_kernel<<<dim3(KTOT / 32, DD / 32), 256>>>(w);
    stage1_mma_kernel<<<dim3(KK / 8, B_), 256, S1_SMEM>>>(x);
    gemm_kernel<<<dim3(DD / BN, MM / BM, SPLIT), 256, GEMM_SMEM>>>();
    reduce_kernel<<<(MM * DD / 4) / 256, 256>>>(out);
}